// round 16
// baseline (speedup 1.0000x reference)
#include <cuda_runtime.h>
#include <math.h>
#include <stdint.h>

// 9x9 max-dilation, SAME padding. cp.async-staged 256x64 tiles with a
// 4-deep intra-CTA load/compute pipeline via mbarrier completion tracking:
//   - CTA = 256 thr; tile = 256 out cols x 64 out rows; raw 264x72 fp32 in
//     dynamic smem (76KB, 2 CTA/SM); read amp 1.125
//   - groups: g0 = raw rows 0..23, g1 = 24..39, g2 = 40..55, g3 = 56..71;
//     after issuing each group, cp.async.mbarrier.arrive.NOINC on mb[k].
//     Per-thread semantics: the arrive fires when ALL of that thread's
//     prior cp.asyncs complete, so mb[k] is cumulative over groups 0..k.
//   - row-stream rs needs raw rows rs*16 .. rs*16+23 -> waits mb[rs] only:
//     rs0 starts after 33% of the tile bytes, rs1 56%, rs2 78%, rs3 100%.
//   - borders via cp.async src-size=0 zero fill (input >= 0 -> 0 is the
//     max identity)
//   - compute: horizontal 9-max from smem (3x LDS.128, halo resident),
//     vertical = two chained van Herk chunks (16 out rows/thread, 1.5
//     hmax evals per output row)
// Input 16x1024x1024x1 fp32.

#define IMG 1024
#define TILE_W 256
#define TILE_H 64
#define RAW_H 72
#define PITCH 264          // floats per smem row
#define QPR 66             // float4 per raw row
#define NTH 256
#define SMEM_BYTES (RAW_H * PITCH * 4)   // 76032

__device__ __forceinline__ float4 max4(float4 a, float4 b) {
    return make_float4(fmaxf(a.x, b.x), fmaxf(a.y, b.y),
                       fmaxf(a.z, b.z), fmaxf(a.w, b.w));
}

__device__ __forceinline__ void cp16(uint32_t dst, const float* src, bool valid) {
    int sz = valid ? 16 : 0;
    asm volatile("cp.async.cg.shared.global [%0], [%1], 16, %2;\n"
                 :: "r"(dst), "l"(src), "r"(sz));
}

__device__ __forceinline__ void mbar_init(uint32_t a, uint32_t cnt) {
    asm volatile("mbarrier.init.shared.b64 [%0], %1;" :: "r"(a), "r"(cnt) : "memory");
}
// .noinc: expected count stays at init; arrive fires when this thread's
// prior cp.asyncs complete. (Plain .arrive increments count -> deadlock.)
__device__ __forceinline__ void cp_arrive_noinc(uint32_t a) {
    asm volatile("cp.async.mbarrier.arrive.noinc.shared.b64 [%0];" :: "r"(a) : "memory");
}
__device__ __forceinline__ void mbar_wait(uint32_t a) {
    asm volatile(
        "{\n\t.reg .pred P;\n"
        "WL_%=:\n\t"
        "mbarrier.try_wait.parity.shared.b64 P, [%0], 0, 0x989680;\n\t"
        "@P bra WD_%=;\n\t"
        "bra WL_%=;\n"
        "WD_%=:\n\t}"
        :: "r"(a) : "memory");
}

// horizontal 9-max of 4 outputs from 12 smem floats at row r, col c0
__device__ __forceinline__ float4 hmax_row(const float* sm, int r, int c0) {
    const float* rp = sm + r * PITCH + c0;
    const float4 a = *(const float4*)rp;
    const float4 b = *(const float4*)(rp + 4);
    const float4 c = *(const float4*)(rp + 8);
    const float q  = fmaxf(fmaxf(b.x, b.y), fmaxf(b.z, b.w));  // v4..v7
    const float s3 = a.w;
    const float s2 = fmaxf(a.z, s3);
    const float s1 = fmaxf(a.y, s2);
    const float s0 = fmaxf(a.x, s1);
    const float p8 = c.x;
    const float p9  = fmaxf(p8, c.y);
    const float p10 = fmaxf(p9, c.z);
    const float p11 = fmaxf(p10, c.w);
    float4 o;
    o.x = fmaxf(fmaxf(s0, q), p8);
    o.y = fmaxf(fmaxf(s1, q), p9);
    o.z = fmaxf(fmaxf(s2, q), p10);
    o.w = fmaxf(fmaxf(s3, q), p11);
    return o;
}

// issue cp.asyncs for raw rows [rbeg, rend)
__device__ __forceinline__ void stage_rows(
    const float* __restrict__ img, uint32_t sbase,
    int x0, int y0, int rbeg, int rend, int tid)
{
    const int n = (rend - rbeg) * QPR;
    #pragma unroll 4
    for (int i = tid; i < n; i += NTH) {
        const int row = rbeg + i / QPR;
        const int q   = i % QPR;
        const int gy = y0 - 4 + row;
        const int gx = x0 - 4 + q * 4;
        const bool v = ((unsigned)gy < (unsigned)IMG) &&
                       ((unsigned)gx <= (unsigned)(IMG - 4));
        const float* src = img + (v ? ((size_t)gy * IMG + gx) : 0);
        cp16(sbase + (uint32_t)(row * QPR + q) * 16u, src, v);
    }
}

__global__ __launch_bounds__(NTH)
void dilate9_kernel(const float* __restrict__ in, float* __restrict__ out) {
    extern __shared__ __align__(16) float sm[];   // RAW_H x PITCH
    __shared__ __align__(8) unsigned long long mbar[4];

    const int bx = blockIdx.x;        // x tile (0..3)
    const int by = blockIdx.y;        // y tile (0..15)
    const int bz = blockIdx.z;        // batch
    const int tid = threadIdx.x;

    const float* img = in  + (size_t)bz * IMG * IMG;
    float*      oimg = out + (size_t)bz * IMG * IMG;

    const int x0 = bx * TILE_W;
    const int y0 = by * TILE_H;

    const uint32_t sbase = (uint32_t)__cvta_generic_to_shared(sm);
    uint32_t mb[4];
    #pragma unroll
    for (int k = 0; k < 4; k++)
        mb[k] = (uint32_t)__cvta_generic_to_shared(&mbar[k]);

    if (tid == 0) {
        #pragma unroll
        for (int k = 0; k < 4; k++) mbar_init(mb[k], NTH);
    }
    __syncthreads();   // mbarrier init visible before any arrive

    // ---- 4-group staged load; mb[k] cumulative over groups 0..k ----
    stage_rows(img, sbase, x0, y0,  0, 24, tid);  cp_arrive_noinc(mb[0]);
    stage_rows(img, sbase, x0, y0, 24, 40, tid);  cp_arrive_noinc(mb[1]);
    stage_rows(img, sbase, x0, y0, 40, 56, tid);  cp_arrive_noinc(mb[2]);
    stage_rows(img, sbase, x0, y0, 56, 72, tid);  cp_arrive_noinc(mb[3]);

    // ---- compute: 64 col groups x 4 row streams of 16 out rows ----
    const int g  = tid & 63;          // col group: 4 cols (16B stride, no conflicts)
    const int rs = tid >> 6;          // row stream 0..3
    const int c0 = g * 4;             // smem col of first window element
    const int r0 = rs * 16;           // first raw row of stream

    // rs needs raw rows r0 .. r0+23: covered by cumulative mb[rs]
    mbar_wait(mb[rs]);

    // chunk 1: suffix over hm rows r0..r0+7
    float4 S[8];
    #pragma unroll
    for (int j = 0; j < 8; j++) S[j] = hmax_row(sm, r0 + j, c0);
    #pragma unroll
    for (int j = 6; j >= 0; j--) S[j] = max4(S[j], S[j + 1]);

    // chunk 1 stream: hm rows r0+8..r0+15 (saved in H), emit out rows 0..7
    float4 H[8];
    float4 P;
    const int oy0 = y0 + rs * 16;
    #pragma unroll
    for (int t = 0; t < 8; t++) {
        H[t] = hmax_row(sm, r0 + 8 + t, c0);
        P = (t == 0) ? H[t] : max4(P, H[t]);
        const float4 o = max4(S[t], P);
        *(float4*)(oimg + (size_t)(oy0 + t) * IMG + x0 + c0) = o;
    }

    // chunk 2: suffix of H in place (H[t] = max of original H[t..7])
    #pragma unroll
    for (int j = 6; j >= 0; j--) H[j] = max4(H[j], H[j + 1]);

    // chunk 2 stream: hm rows r0+16..r0+23, emit out rows 8..15
    #pragma unroll
    for (int t = 0; t < 8; t++) {
        const float4 hm = hmax_row(sm, r0 + 16 + t, c0);
        P = (t == 0) ? hm : max4(P, hm);
        const float4 o = max4(H[t], P);
        *(float4*)(oimg + (size_t)(oy0 + 8 + t) * IMG + x0 + c0) = o;
    }
}

extern "C" void kernel_launch(void* const* d_in, const int* in_sizes, int n_in,
                              void* d_out, int out_size) {
    const float* in = (const float*)d_in[0];
    float* out = (float*)d_out;
    const int batch = in_sizes[0] / (IMG * IMG);

    cudaFuncSetAttribute(dilate9_kernel,
                         cudaFuncAttributeMaxDynamicSharedMemorySize, SMEM_BYTES);

    dim3 grid(IMG / TILE_W, IMG / TILE_H, batch);
    dilate9_kernel<<<grid, NTH, SMEM_BYTES>>>(in, out);
}

// round 17
// speedup vs baseline: 1.0344x; 1.0344x over previous
#include <cuda_runtime.h>
#include <math.h>
#include <stdint.h>

// 9x9 max-dilation, SAME padding. cp.async-staged 256x64 tiles with
// 2-group intra-CTA load/compute pipeline (round-15 winner) plus:
//   - divide-free warp-per-row staging loops (no i/66, i%66)
//   - templated guard: interior CTAs stage with zero per-copy checks
// Structure:
//   - CTA = 256 thr; tile = 256 out cols x 64 out rows; raw 264x72 fp32 in
//     dynamic smem (76KB, 2 CTA/SM); read amp 1.125
//   - group 0 = raw rows 0..39 -> mb0; group 1 = rows 40..71 -> mb1
//     (cp.async.mbarrier.arrive.NOINC; mb1 cumulative over both groups)
//   - row-streams 0..1 (tid<128) wait mb0 only; 2..3 wait mb1
//   - borders via cp.async src-size=0 zero fill (input >= 0 -> 0 is the
//     max identity)
//   - compute: horizontal 9-max from smem (3x LDS.128, halo resident),
//     vertical = two chained van Herk chunks (16 out rows/thread)
// Input 16x1024x1024x1 fp32.

#define IMG 1024
#define TILE_W 256
#define TILE_H 64
#define RAW_H 72
#define PITCH 264          // floats per smem row
#define QPR 66             // float4 per raw row
#define NTH 256
#define NWARP 8
#define G0_ROWS 40
#define SMEM_BYTES (RAW_H * PITCH * 4)   // 76032

__device__ __forceinline__ float4 max4(float4 a, float4 b) {
    return make_float4(fmaxf(a.x, b.x), fmaxf(a.y, b.y),
                       fmaxf(a.z, b.z), fmaxf(a.w, b.w));
}

__device__ __forceinline__ void cp16(uint32_t dst, const float* src, bool valid) {
    int sz = valid ? 16 : 0;
    asm volatile("cp.async.cg.shared.global [%0], [%1], 16, %2;\n"
                 :: "r"(dst), "l"(src), "r"(sz));
}
__device__ __forceinline__ void cp16u(uint32_t dst, const float* src) {
    asm volatile("cp.async.cg.shared.global [%0], [%1], 16;\n"
                 :: "r"(dst), "l"(src));
}

__device__ __forceinline__ void mbar_init(uint32_t a, uint32_t cnt) {
    asm volatile("mbarrier.init.shared.b64 [%0], %1;" :: "r"(a), "r"(cnt) : "memory");
}
// .noinc: expected count stays at init; arrive fires when this thread's
// prior cp.asyncs complete.
__device__ __forceinline__ void cp_arrive_noinc(uint32_t a) {
    asm volatile("cp.async.mbarrier.arrive.noinc.shared.b64 [%0];" :: "r"(a) : "memory");
}
__device__ __forceinline__ void mbar_wait(uint32_t a) {
    asm volatile(
        "{\n\t.reg .pred P;\n"
        "WL_%=:\n\t"
        "mbarrier.try_wait.parity.shared.b64 P, [%0], 0, 0x989680;\n\t"
        "@P bra WD_%=;\n\t"
        "bra WL_%=;\n"
        "WD_%=:\n\t}"
        :: "r"(a) : "memory");
}

// horizontal 9-max of 4 outputs from 12 smem floats at row r, col c0
__device__ __forceinline__ float4 hmax_row(const float* sm, int r, int c0) {
    const float* rp = sm + r * PITCH + c0;
    const float4 a = *(const float4*)rp;
    const float4 b = *(const float4*)(rp + 4);
    const float4 c = *(const float4*)(rp + 8);
    const float q  = fmaxf(fmaxf(b.x, b.y), fmaxf(b.z, b.w));  // v4..v7
    const float s3 = a.w;
    const float s2 = fmaxf(a.z, s3);
    const float s1 = fmaxf(a.y, s2);
    const float s0 = fmaxf(a.x, s1);
    const float p8 = c.x;
    const float p9  = fmaxf(p8, c.y);
    const float p10 = fmaxf(p9, c.z);
    const float p11 = fmaxf(p10, c.w);
    float4 o;
    o.x = fmaxf(fmaxf(s0, q), p8);
    o.y = fmaxf(fmaxf(s1, q), p9);
    o.z = fmaxf(fmaxf(s2, q), p10);
    o.w = fmaxf(fmaxf(s3, q), p11);
    return o;
}

// stage raw rows [rbeg, rend) with warp-per-row, lane-per-quad loops.
// GUARD=false: all addresses known in-bounds, zero checks.
template<bool GUARD>
__device__ __forceinline__ void stage_rows(
    const float* __restrict__ img, uint32_t sbase,
    int x0, int y0, int rbeg, int rend, int wid, int lane)
{
    for (int row = rbeg + wid; row < rend; row += NWARP) {
        const int gy = y0 - 4 + row;
        const uint32_t drow = sbase + (uint32_t)(row * QPR) * 16u;
        const float* srow = img + (size_t)gy * IMG + (x0 - 4);
        if (GUARD) {
            const bool rowok = (unsigned)gy < (unsigned)IMG;
            #pragma unroll 3
            for (int q = lane; q < QPR; q += 32) {
                const int gx = x0 - 4 + q * 4;
                const bool v = rowok && ((unsigned)gx <= (unsigned)(IMG - 4));
                cp16(drow + (uint32_t)q * 16u, srow + (v ? q * 4 : (4 - x0)), v);
            }
        } else {
            #pragma unroll 3
            for (int q = lane; q < QPR; q += 32)
                cp16u(drow + (uint32_t)q * 16u, srow + q * 4);
        }
    }
}

template<bool GUARD>
__device__ __forceinline__ void run_tile(
    const float* __restrict__ img, float* __restrict__ oimg,
    int x0, int y0, int tid, uint32_t sbase, const float* sm,
    uint32_t mb0, uint32_t mb1)
{
    const int lane = tid & 31;
    const int wid  = tid >> 5;

    // ---- group 0: raw rows 0..39 ----
    stage_rows<GUARD>(img, sbase, x0, y0, 0, G0_ROWS, wid, lane);
    cp_arrive_noinc(mb0);
    // ---- group 1: raw rows 40..71 ----
    stage_rows<GUARD>(img, sbase, x0, y0, G0_ROWS, RAW_H, wid, lane);
    cp_arrive_noinc(mb1);

    // ---- compute: 64 col groups x 4 row streams of 16 out rows ----
    const int g  = tid & 63;
    const int rs = tid >> 6;
    const int c0 = g * 4;
    const int r0 = rs * 16;

    if (rs < 2) mbar_wait(mb0);
    else        mbar_wait(mb1);

    // chunk 1: suffix over hm rows r0..r0+7
    float4 S[8];
    #pragma unroll
    for (int j = 0; j < 8; j++) S[j] = hmax_row(sm, r0 + j, c0);
    #pragma unroll
    for (int j = 6; j >= 0; j--) S[j] = max4(S[j], S[j + 1]);

    // chunk 1 stream: hm rows r0+8..r0+15 (saved in H), emit out rows 0..7
    float4 H[8];
    float4 P;
    const int oy0 = y0 + rs * 16;
    #pragma unroll
    for (int t = 0; t < 8; t++) {
        H[t] = hmax_row(sm, r0 + 8 + t, c0);
        P = (t == 0) ? H[t] : max4(P, H[t]);
        const float4 o = max4(S[t], P);
        *(float4*)(oimg + (size_t)(oy0 + t) * IMG + x0 + c0) = o;
    }

    // chunk 2: suffix of H in place
    #pragma unroll
    for (int j = 6; j >= 0; j--) H[j] = max4(H[j], H[j + 1]);

    // chunk 2 stream: hm rows r0+16..r0+23, emit out rows 8..15
    #pragma unroll
    for (int t = 0; t < 8; t++) {
        const float4 hm = hmax_row(sm, r0 + 16 + t, c0);
        P = (t == 0) ? hm : max4(P, hm);
        const float4 o = max4(H[t], P);
        *(float4*)(oimg + (size_t)(oy0 + 8 + t) * IMG + x0 + c0) = o;
    }
}

__global__ __launch_bounds__(NTH)
void dilate9_kernel(const float* __restrict__ in, float* __restrict__ out) {
    extern __shared__ __align__(16) float sm[];   // RAW_H x PITCH
    __shared__ __align__(8) unsigned long long mbar[2];

    const int bx = blockIdx.x;        // x tile (0..3)
    const int by = blockIdx.y;        // y tile (0..15)
    const int bz = blockIdx.z;        // batch
    const int tid = threadIdx.x;

    const float* img = in  + (size_t)bz * IMG * IMG;
    float*      oimg = out + (size_t)bz * IMG * IMG;

    const int x0 = bx * TILE_W;
    const int y0 = by * TILE_H;

    const uint32_t sbase = (uint32_t)__cvta_generic_to_shared(sm);
    const uint32_t mb0 = (uint32_t)__cvta_generic_to_shared(&mbar[0]);
    const uint32_t mb1 = (uint32_t)__cvta_generic_to_shared(&mbar[1]);

    if (tid == 0) {
        mbar_init(mb0, NTH);
        mbar_init(mb1, NTH);
    }
    __syncthreads();   // mbarrier init visible before any arrive

    // interior tiles: raw cols x0-4..x0+259 and rows y0-4..y0+67 in-bounds
    const bool interior = (bx > 0) && (bx < IMG / TILE_W - 1) &&
                          (by > 0) && (by < IMG / TILE_H - 1);
    if (interior)
        run_tile<false>(img, oimg, x0, y0, tid, sbase, sm, mb0, mb1);
    else
        run_tile<true>(img, oimg, x0, y0, tid, sbase, sm, mb0, mb1);
}

extern "C" void kernel_launch(void* const* d_in, const int* in_sizes, int n_in,
                              void* d_out, int out_size) {
    const float* in = (const float*)d_in[0];
    float* out = (float*)d_out;
    const int batch = in_sizes[0] / (IMG * IMG);

    cudaFuncSetAttribute(dilate9_kernel,
                         cudaFuncAttributeMaxDynamicSharedMemorySize, SMEM_BYTES);

    dim3 grid(IMG / TILE_W, IMG / TILE_H, batch);
    dilate9_kernel<<<grid, NTH, SMEM_BYTES>>>(in, out);
}